// round 2
// baseline (speedup 1.0000x reference)
#include <cuda_runtime.h>
#include <math.h>

#define NN 16384
#define LL 50
#define EE 64
#define CEDIM 128

// ---------------- device scratch (static allocations are allowed) ----------------
__device__ float g_post[NN * EE];                    // 4 MB
__device__ float g_o[(size_t)NN * LL * EE];          // 210 MB
__device__ float g_logits[NN * LL];                  // 3.3 MB
__device__ int   g_pairs[NN * LL];                   // 3.3 MB
__device__ int   g_count;

__global__ void k_reset() { g_count = 0; }

__global__ void k_build_pairs(const int* __restrict__ lengths) {
    int n = blockIdx.x * blockDim.x + threadIdx.x;
    if (n >= NN) return;
    int len = lengths[n];
    int base = atomicAdd(&g_count, len);
    for (int l = 0; l < len; ++l) g_pairs[base + l] = (n << 6) | l;
}

// ---------------- 64x64 tile GEMM, 256 threads, 4x4 register blocking ----------------
__device__ __forceinline__ void fma4(float4& a, float s, const float4 b) {
    a.x = fmaf(s, b.x, a.x); a.y = fmaf(s, b.y, a.y);
    a.z = fmaf(s, b.z, a.z); a.w = fmaf(s, b.w, a.w);
}

// out[i][f] = relu(bias[f] + sum_{k<Ka} inA[i][k]*W[k][f] + sum_{k<Kb} inB[i][k]*W[Ka+k][f])
// i in [0,64), f in [0,64). Thread: fslot=tid&15 (4 f's), islot=tid>>4 (items islot+16j).
__device__ __forceinline__ void tile_gemm(
    const float* __restrict__ W, const float* __restrict__ bias,
    const float* __restrict__ inA, int ldA, int Ka,
    const float* __restrict__ inB, int ldB, int Kb,
    float* __restrict__ out, int ldO, int tid)
{
    const int fslot = tid & 15, islot = tid >> 4;
    float4 acc[4];
    float4 b4 = ((const float4*)bias)[fslot];
    acc[0] = b4; acc[1] = b4; acc[2] = b4; acc[3] = b4;

    const float* Wp = W + fslot * 4;
    for (int k = 0; k < Ka; k += 4) {
        float4 w0 = *(const float4*)(Wp + (k + 0) * 64);
        float4 w1 = *(const float4*)(Wp + (k + 1) * 64);
        float4 w2 = *(const float4*)(Wp + (k + 2) * 64);
        float4 w3 = *(const float4*)(Wp + (k + 3) * 64);
        #pragma unroll
        for (int j = 0; j < 4; ++j) {
            float4 x = *(const float4*)(inA + (islot + 16 * j) * ldA + k);
            fma4(acc[j], x.x, w0); fma4(acc[j], x.y, w1);
            fma4(acc[j], x.z, w2); fma4(acc[j], x.w, w3);
        }
    }
    if (inB) {
        const float* Wq = W + Ka * 64 + fslot * 4;
        for (int k = 0; k < Kb; k += 4) {
            float4 w0 = *(const float4*)(Wq + (k + 0) * 64);
            float4 w1 = *(const float4*)(Wq + (k + 1) * 64);
            float4 w2 = *(const float4*)(Wq + (k + 2) * 64);
            float4 w3 = *(const float4*)(Wq + (k + 3) * 64);
            #pragma unroll
            for (int j = 0; j < 4; ++j) {
                float4 x = *(const float4*)(inB + (islot + 16 * j) * ldB + k);
                fma4(acc[j], x.x, w0); fma4(acc[j], x.y, w1);
                fma4(acc[j], x.z, w2); fma4(acc[j], x.w, w3);
            }
        }
    }
    #pragma unroll
    for (int j = 0; j < 4; ++j) {
        float4 v = acc[j];
        v.x = fmaxf(v.x, 0.f); v.y = fmaxf(v.y, 0.f);
        v.z = fmaxf(v.z, 0.f); v.w = fmaxf(v.w, 0.f);
        *(float4*)(out + (islot + 16 * j) * ldO + fslot * 4) = v;
    }
}

// A2 layer + A3 logit: a2 = relu(W*a1+b); logit = a2 . A3 + bA3 (a2 stays in registers)
__device__ __forceinline__ void tile_a2_logit(
    const float* __restrict__ W, const float* __restrict__ bias,
    const float* __restrict__ inA, int ldA, int Ka,
    const float* __restrict__ A3, float bA3,
    const int* __restrict__ pn, const int* __restrict__ pl, int tid)
{
    const int fslot = tid & 15, islot = tid >> 4;
    float4 acc[4];
    float4 b4 = ((const float4*)bias)[fslot];
    acc[0] = b4; acc[1] = b4; acc[2] = b4; acc[3] = b4;

    const float* Wp = W + fslot * 4;
    for (int k = 0; k < Ka; k += 4) {
        float4 w0 = *(const float4*)(Wp + (k + 0) * 64);
        float4 w1 = *(const float4*)(Wp + (k + 1) * 64);
        float4 w2 = *(const float4*)(Wp + (k + 2) * 64);
        float4 w3 = *(const float4*)(Wp + (k + 3) * 64);
        #pragma unroll
        for (int j = 0; j < 4; ++j) {
            float4 x = *(const float4*)(inA + (islot + 16 * j) * ldA + k);
            fma4(acc[j], x.x, w0); fma4(acc[j], x.y, w1);
            fma4(acc[j], x.z, w2); fma4(acc[j], x.w, w3);
        }
    }
    float4 a3 = ((const float4*)A3)[fslot];
    #pragma unroll
    for (int j = 0; j < 4; ++j) {
        float p = fmaxf(acc[j].x, 0.f) * a3.x + fmaxf(acc[j].y, 0.f) * a3.y +
                  fmaxf(acc[j].z, 0.f) * a3.z + fmaxf(acc[j].w, 0.f) * a3.w;
        #pragma unroll
        for (int off = 8; off >= 1; off >>= 1)
            p += __shfl_xor_sync(0xffffffffu, p, off);   // reduce over the 16 fslot lanes
        if (fslot == 0) {
            int it = islot + 16 * j;
            g_logits[pn[it] * LL + pl[it]] = p + bA3;
        }
    }
}

// ---------------- post kernel: post = relu(content[pr_content] @ We + bWe) ----------------
struct SmemPost {
    float We[128 * 64];
    float bWe[64];
    float in[64 * 128];
    int   cix[64];
};

__global__ void __launch_bounds__(256, 1) k_post(
    const float* __restrict__ content, const float* __restrict__ Weg,
    const float* __restrict__ bWeg, const int* __restrict__ pr_content)
{
    extern __shared__ float smem_raw[];
    SmemPost& s = *(SmemPost*)smem_raw;
    int tid = threadIdx.x;
    for (int i = tid; i < 128 * 64; i += 256) s.We[i] = Weg[i];
    if (tid < 64) { s.bWe[tid] = bWeg[tid]; s.cix[tid] = pr_content[blockIdx.x * 64 + tid]; }
    __syncthreads();
    for (int v = tid; v < 64 * 32; v += 256) {
        int it = v >> 5, sub = v & 31;
        ((float4*)(s.in + it * 128))[sub] =
            ((const float4*)(content + (size_t)s.cix[it] * 128))[sub];
    }
    __syncthreads();
    tile_gemm(s.We, s.bWe, s.in, 128, 128, nullptr, 0, 0,
              g_post + (size_t)blockIdx.x * 64 * 64, 64, tid);
}

// ---------------- main kernel: per-pair x -> o -> a1 -> a2 -> logit ----------------
struct SmemMain {
    float W1[128 * 64];
    float A1[128 * 64];
    float W2[64 * 64];
    float A2[64 * 64];
    float b1[64], b2[64], bA1[64], bA2[64], A3[64];
    float in[64 * 128];
    float act[64 * 64];
    float o[64 * 64];
    float post[64 * 64];
    int pn[64], pl[64], uix[64], rix[64];
};

__global__ void __launch_bounds__(256, 1) k_main(
    const float* __restrict__ u2e, const float* __restrict__ r2e,
    const float* __restrict__ W1g, const float* __restrict__ b1g,
    const float* __restrict__ W2g, const float* __restrict__ b2g,
    const float* __restrict__ A1g, const float* __restrict__ bA1g,
    const float* __restrict__ A2g, const float* __restrict__ bA2g,
    const float* __restrict__ A3g, const float* __restrict__ bA3g,
    const int* __restrict__ pu, const int* __restrict__ pr)
{
    extern __shared__ float smem_raw[];
    SmemMain& s = *(SmemMain*)smem_raw;
    int tid = threadIdx.x;

    for (int i = tid; i < 128 * 64; i += 256) { s.W1[i] = W1g[i]; s.A1[i] = A1g[i]; }
    for (int i = tid; i < 64 * 64; i += 256)  { s.W2[i] = W2g[i]; s.A2[i] = A2g[i]; }
    if (tid < 64) {
        s.b1[tid] = b1g[tid]; s.b2[tid] = b2g[tid];
        s.bA1[tid] = bA1g[tid]; s.bA2[tid] = bA2g[tid]; s.A3[tid] = A3g[tid];
    }
    float bA3 = bA3g[0];
    __syncthreads();

    int total = g_count;
    int ntiles = (total + 63) >> 6;

    for (int t = blockIdx.x; t < ntiles; t += gridDim.x) {
        int e0 = t * 64;
        if (tid < 64) {
            int e = e0 + tid;
            int pair = (e < total) ? g_pairs[e] : 0;   // pad -> (0,0), benign duplicate
            int n = pair >> 6, l = pair & 63;
            s.pn[tid] = n; s.pl[tid] = l;
            s.uix[tid] = pu[n * LL + l];
            s.rix[tid] = pr[n * LL + l];
        }
        __syncthreads();

        // gather [u;r] rows (64x128) and post rows (64x64)
        for (int v = tid; v < 64 * 32 + 64 * 16; v += 256) {
            if (v < 64 * 32) {
                int it = v >> 5, sub = v & 31;
                float4 val;
                if (sub < 16) val = ((const float4*)(u2e + (size_t)s.uix[it] * 64))[sub];
                else          val = ((const float4*)(r2e + (size_t)s.rix[it] * 64))[sub - 16];
                ((float4*)(s.in + it * 128))[sub] = val;
            } else {
                int w = v - 64 * 32; int it = w >> 4, sub = w & 15;
                ((float4*)(s.post + it * 64))[sub] =
                    ((const float4*)(g_post + s.pn[it] * 64))[sub];
            }
        }
        __syncthreads();

        tile_gemm(s.W1, s.b1, s.in, 128, 128, nullptr, 0, 0, s.act, 64, tid);  // x
        __syncthreads();
        tile_gemm(s.W2, s.b2, s.act, 64, 64, nullptr, 0, 0, s.o, 64, tid);     // o
        __syncthreads();

        // write o to global (read later by finalize), then A1 (both only read s.o)
        for (int v = tid; v < 64 * 16; v += 256) {
            int it = v >> 4, sub = v & 15;
            ((float4*)(g_o + ((size_t)s.pn[it] * LL + s.pl[it]) * 64))[sub] =
                ((const float4*)(s.o + it * 64))[sub];
        }
        tile_gemm(s.A1, s.bA1, s.o, 64, 64, s.post, 64, 64, s.act, 64, tid);   // a1
        __syncthreads();
        tile_a2_logit(s.A2, s.bA2, s.act, 64, 64, s.A3, bA3, s.pn, s.pl, tid); // logit
        __syncthreads();
    }
}

// ---------------- finalize: softmax + hist + output layer ----------------
struct SmemFin {
    float Ow[128 * 64];
    float bOw[64];
    float att[64];
    float red[256];
    float hist[64];
    float post[64];
};

__global__ void __launch_bounds__(256, 1) k_fin(
    const float* __restrict__ Owg, const float* __restrict__ bOwg,
    const int* __restrict__ lengths, float* __restrict__ out)
{
    extern __shared__ float smem_raw[];
    SmemFin& s = *(SmemFin*)smem_raw;
    int tid = threadIdx.x;
    for (int i = tid; i < 128 * 64; i += 256) s.Ow[i] = Owg[i];
    if (tid < 64) s.bOw[tid] = bOwg[tid];
    __syncthreads();

    for (int n = blockIdx.x; n < NN; n += gridDim.x) {
        int len = lengths[n];
        if (tid < 32) {
            int lane = tid;
            float l0 = (lane < len)      ? g_logits[n * LL + lane]      : -INFINITY;
            float l1 = (lane + 32 < len) ? g_logits[n * LL + lane + 32] : -INFINITY;
            float m = fmaxf(l0, l1);
            #pragma unroll
            for (int off = 16; off >= 1; off >>= 1)
                m = fmaxf(m, __shfl_xor_sync(0xffffffffu, m, off));
            float e0 = (lane < len)      ? expf(l0 - m) : 0.f;
            float e1 = (lane + 32 < len) ? expf(l1 - m) : 0.f;
            float sum = e0 + e1;
            #pragma unroll
            for (int off = 16; off >= 1; off >>= 1)
                sum += __shfl_xor_sync(0xffffffffu, sum, off);
            float inv = 1.f / sum;
            s.att[lane] = e0 * inv; s.att[lane + 32] = e1 * inv;
        }
        if (tid >= 64 && tid < 128) s.post[tid - 64] = g_post[n * 64 + (tid - 64)];
        __syncthreads();

        int f = tid & 63, g = tid >> 6;
        float partial = 0.f;
        for (int l = g; l < len; l += 4)
            partial += s.att[l] * g_o[((size_t)n * LL + l) * 64 + f];
        s.red[g * 64 + f] = partial;
        __syncthreads();
        if (tid < 64)
            s.hist[tid] = s.red[tid] + s.red[64 + tid] + s.red[128 + tid] + s.red[192 + tid];
        __syncthreads();

        float p2 = 0.f;
        int k0 = g * 32;
        #pragma unroll 8
        for (int k = k0; k < k0 + 32; ++k) {
            float x = (k < 64) ? s.hist[k] : s.post[k - 64];
            p2 = fmaf(x, s.Ow[k * 64 + f], p2);
        }
        s.red[g * 64 + f] = p2;
        __syncthreads();
        if (tid < 64)
            out[n * 64 + tid] = fmaxf(
                s.bOw[tid] + s.red[tid] + s.red[64 + tid] + s.red[128 + tid] + s.red[192 + tid],
                0.f);
        __syncthreads();
    }
}

// ---------------- launch ----------------
extern "C" void kernel_launch(void* const* d_in, const int* in_sizes, int n_in,
                              void* d_out, int out_size)
{
    const float* u2e     = (const float*)d_in[0];
    const float* r2e     = (const float*)d_in[1];
    const float* content = (const float*)d_in[2];
    const float* We_w = (const float*)d_in[3];  const float* We_b = (const float*)d_in[4];
    const float* W1_w = (const float*)d_in[5];  const float* W1_b = (const float*)d_in[6];
    const float* W2_w = (const float*)d_in[7];  const float* W2_b = (const float*)d_in[8];
    const float* A1_w = (const float*)d_in[9];  const float* A1_b = (const float*)d_in[10];
    const float* A2_w = (const float*)d_in[11]; const float* A2_b = (const float*)d_in[12];
    const float* A3_w = (const float*)d_in[13]; const float* A3_b = (const float*)d_in[14];
    const float* Ow_w = (const float*)d_in[15]; const float* Ow_b = (const float*)d_in[16];
    const int* pu      = (const int*)d_in[18];
    const int* pr      = (const int*)d_in[19];
    const int* lengths = (const int*)d_in[20];
    const int* prc     = (const int*)d_in[21];
    float* out = (float*)d_out;

    static int nsm = 0;
    if (nsm == 0) {
        cudaDeviceGetAttribute(&nsm, cudaDevAttrMultiProcessorCount, 0);
        cudaFuncSetAttribute(k_main, cudaFuncAttributeMaxDynamicSharedMemorySize, (int)sizeof(SmemMain));
        cudaFuncSetAttribute(k_post, cudaFuncAttributeMaxDynamicSharedMemorySize, (int)sizeof(SmemPost));
        cudaFuncSetAttribute(k_fin,  cudaFuncAttributeMaxDynamicSharedMemorySize, (int)sizeof(SmemFin));
    }

    k_reset<<<1, 1>>>();
    k_build_pairs<<<NN / 256, 256>>>(lengths);
    k_post<<<NN / 64, 256, sizeof(SmemPost)>>>(content, We_w, We_b, prc);
    k_main<<<nsm, 256, sizeof(SmemMain)>>>(u2e, r2e, W1_w, W1_b, W2_w, W2_b,
                                           A1_w, A1_b, A2_w, A2_b, A3_w, A3_b, pu, pr);
    k_fin<<<nsm, 256, sizeof(SmemFin)>>>(Ow_w, Ow_b, lengths, out);
}